// round 15
// baseline (speedup 1.0000x reference)
#include <cuda_runtime.h>

// Shapes: seq=64 steps (orig B), only batch-row t=255 of T=256 matters.
#define STEPS 64
#define HID   1024
#define G4    4096
#define TT    256
#define DD    1024
#define CC    27
#define NB    128          // recurrence CTAs (1/SM, co-resident)
#define NCH   8            // GEMM K-split chunks
#define KC    128          // k per chunk
#define SENT  0xFFC0DEADu  // NaN payload: impossible LSTM output bit pattern

typedef unsigned long long ull;
typedef unsigned int uint;

// ---- scratch (device globals; no allocation) ----
__device__ __align__(16) float g_xgp[(long)NCH * STEPS * G4];  // gate-preact partials
__device__ __align__(16) float g_h1 [STEPS * HID];
__device__ __align__(16) float g_h2 [STEPS * HID];
__device__ __align__(16) float g_zp [NCH * STEPS * 512];       // fc1 partials

__global__ void reset_kernel() {
    int i = blockIdx.x * 256 + threadIdx.x;   // 256x256 = 65536 = STEPS*HID
    ((uint*)g_h1)[i] = SENT;
    ((uint*)g_h2)[i] = SENT;
}

__device__ __forceinline__ float sigf(float x)     { return 1.0f / (1.0f + __expf(-x)); }
__device__ __forceinline__ float tanhfast(float x) { return 2.0f / (1.0f + __expf(-2.0f * x)) - 1.0f; }

__device__ __forceinline__ ull fma2(ull a, ull b, ull c) {
    ull d;
    asm("fma.rn.f32x2 %0, %1, %2, %3;" : "=l"(d) : "l"(a), "l"(b), "l"(c));
    return d;
}
__device__ __forceinline__ float2 unpack2(ull v) {
    float2 f;
    asm("mov.b64 {%0, %1}, %2;" : "=f"(f.x), "=f"(f.y) : "l"(v));
    return f;
}
// morally-strong relaxed atomics (gpu scope) for the racing h exchange
__device__ __forceinline__ ull ld_relaxed_b64(const ull* p) {
    ull v;
    asm volatile("ld.relaxed.gpu.global.b64 %0, [%1];" : "=l"(v) : "l"(p) : "memory");
    return v;
}
__device__ __forceinline__ void st_relaxed_f32(float* p, float v) {
    asm volatile("st.relaxed.gpu.global.f32 [%0], %1;" :: "l"(p), "f"(v) : "memory");
}
__device__ __forceinline__ void cp_async16(void* smem_dst, const void* gptr) {
    uint a = (uint)__cvta_generic_to_shared(smem_dst);
    asm volatile("cp.async.cg.shared.global [%0], [%1], 16;" :: "r"(a), "l"(gptr) : "memory");
}
#define CP_COMMIT()    asm volatile("cp.async.commit_group;" ::: "memory")
#define CP_WAIT(n)     asm volatile("cp.async.wait_group " #n ";" ::: "memory")

// ============================================================
// K-split (x8) tiled GEMM — ALL 4 W tiles prefetched via cp.async
// at kernel start (4 groups, 128B in flight per thread); X via
// register prefetch + smem transpose (double-buffered).
//   mode 0: X = x[:,255,:] (stride T*D), rows=4096 -> g_xgp   grid 1024
//   mode 1: X = g_h1,                    rows=4096 -> g_xgp   grid 1024
//   mode 2: X = g_h2,                    rows=512  -> g_zp    grid 128
// 128 threads, 32-row x 64-s tile, thread tile 4x4.
// ============================================================
__global__ __launch_bounds__(128)
void gemmcp_k(int mode, const float* __restrict__ xin, const float* __restrict__ W)
{
    __shared__ __align__(16) float WsR[4][32 * 36];   // [tile][row*36 + k] 18.4KB
    __shared__ __align__(16) float Xs [2][32][68];    // [buf][k][s]        17.4KB

    const float* X;
    long xbase, xstride;
    float* pout;
    int nrows, ntiles;
    if (mode == 0)      { X = xin;  xbase = 255L * DD; xstride = (long)TT * DD; pout = g_xgp; nrows = G4;  ntiles = 128; }
    else if (mode == 1) { X = g_h1; xbase = 0;         xstride = HID;           pout = g_xgp; nrows = G4;  ntiles = 128; }
    else                { X = g_h2; xbase = 0;         xstride = HID;           pout = g_zp;  nrows = 512; ntiles = 16;  }

    const int chunk = blockIdx.x / ntiles;
    const int rb    = (blockIdx.x % ntiles) * 32;
    pout += (long)chunk * STEPS * nrows;

    const int t  = threadIdx.x;
    const int tr = t >> 4;
    const int tc = t & 15;
    const int k0 = chunk * KC;

    // W cp.async coords: 256 16B-chunks per tile, 2 per thread
    const int wr0 = t >> 3,          wk0 = (t & 7) * 4;
    const int wr1 = (t + 128) >> 3,  wk1 = ((t + 128) & 7) * 4;
    // X reg-prefetch coords: 4 float4 per thread
    int xs_s[4], xs_kq[4];
#pragma unroll
    for (int i = 0; i < 4; i++) { int e = t + i * 128; xs_s[i] = e >> 3; xs_kq[i] = (e & 7) * 4; }

    // prologue: cp.async ALL FOUR W tiles (one group each)
#pragma unroll
    for (int tile = 0; tile < 4; tile++) {
        const int kt = k0 + tile * 32;
        cp_async16(&WsR[tile][wr0 * 36 + wk0], &W[(long)(rb + wr0) * 1024 + kt + wk0]);
        cp_async16(&WsR[tile][wr1 * 36 + wk1], &W[(long)(rb + wr1) * 1024 + kt + wk1]);
        CP_COMMIT();
    }
    // X tile0 into regs
    float4 xA[4];
#pragma unroll
    for (int i = 0; i < 4; i++)
        xA[i] = *(const float4*)&X[xbase + (long)xs_s[i] * xstride + k0 + xs_kq[i]];

    float acc[4][4];
#pragma unroll
    for (int i = 0; i < 4; i++)
#pragma unroll
        for (int j = 0; j < 4; j++) acc[i][j] = 0.0f;

#pragma unroll
    for (int tile = 0; tile < 4; tile++) {
        const int buf = tile & 1;
        // commit X tile (transpose scatter into Xs[buf])
#pragma unroll
        for (int i = 0; i < 4; i++) {
            Xs[buf][xs_kq[i] + 0][xs_s[i]] = xA[i].x;
            Xs[buf][xs_kq[i] + 1][xs_s[i]] = xA[i].y;
            Xs[buf][xs_kq[i] + 2][xs_s[i]] = xA[i].z;
            Xs[buf][xs_kq[i] + 3][xs_s[i]] = xA[i].w;
        }
        // retire this tile's W group (others stay in flight)
        if (tile == 0)      CP_WAIT(3);
        else if (tile == 1) CP_WAIT(2);
        else if (tile == 2) CP_WAIT(1);
        else                CP_WAIT(0);
        __syncthreads();   // W tile + X tile visible to all

        // reg-load X tile+1 (overlaps FMA below)
        if (tile < 3) {
            const int kt = k0 + (tile + 1) * 32;
#pragma unroll
            for (int i = 0; i < 4; i++)
                xA[i] = *(const float4*)&X[xbase + (long)xs_s[i] * xstride + kt + xs_kq[i]];
        }

        // FMA: k-quads; W row-major reads (2 rows/warp -> conflict-free)
#pragma unroll
        for (int kq = 0; kq < 8; kq++) {
            float xf[4][4];   // [q][j]
#pragma unroll
            for (int q = 0; q < 4; q++) {
                float4 v = *(const float4*)&Xs[buf][kq * 4 + q][tc * 4];
                xf[q][0] = v.x; xf[q][1] = v.y; xf[q][2] = v.z; xf[q][3] = v.w;
            }
            float wf[4][4];   // [i][q]
#pragma unroll
            for (int i = 0; i < 4; i++) {
                float4 v = *(const float4*)&WsR[tile][(tr * 4 + i) * 36 + kq * 4];
                wf[i][0] = v.x; wf[i][1] = v.y; wf[i][2] = v.z; wf[i][3] = v.w;
            }
#pragma unroll
            for (int i = 0; i < 4; i++)
#pragma unroll
                for (int j = 0; j < 4; j++) {
                    acc[i][j] = fmaf(wf[i][0], xf[0][j], acc[i][j]);
                    acc[i][j] = fmaf(wf[i][1], xf[1][j], acc[i][j]);
                    acc[i][j] = fmaf(wf[i][2], xf[2][j], acc[i][j]);
                    acc[i][j] = fmaf(wf[i][3], xf[3][j], acc[i][j]);
                }
        }
        __syncthreads();   // Xs buffer reuse guard
    }

#pragma unroll
    for (int i = 0; i < 4; i++) {
        int row = rb + tr * 4 + i;
#pragma unroll
        for (int j = 0; j < 4; j++)
            pout[(long)(tc * 4 + j) * nrows + row] = acc[i][j];
    }
}

// ============================================================
// Persistent LSTM recurrence (R11 structure; activations moved into
// the 16 gate warps — graw now holds ACTIVATED gate values).
// 128 CTAs x 512 threads, Whh in packed-f32x2 registers,
// h exchange via sentinel-polled relaxed b64 atomics, 2 syncs/step.
// ============================================================
__global__ __launch_bounds__(512, 1)
void lstm_rec(const float* __restrict__ Whh,
              const float* __restrict__ ba, const float* __restrict__ bb,
              int layer)
{
    __shared__ __align__(16) float hsh[HID];
    __shared__ float graw[32];   // [unit*4 + gate] — ACTIVATED values

    float* hseq = layer ? g_h2 : g_h1;
    const int r    = blockIdx.x;
    const int t    = threadIdx.x;
    const int lane = t & 31;
    const int w    = t >> 5;       // 0..15
    const int g    = w & 3;
    const int jh   = w >> 2;       // 0..3
    const int rowbase = (g << 10) + (r << 3) + (jh << 1);   // 2 rows

    ull w0[16], w1[16];
#pragma unroll
    for (int p = 0; p < 16; p++) {
        long o = (long)rowbase * 1024 + p * 64 + lane * 2;
        w0[p] = *(const ull*)(Whh + o);
        w1[p] = *(const ull*)(Whh + o + 1024);
    }
    float2 bias = make_float2(0.f, 0.f);
    if (lane == 16) {
        bias.x = ba[rowbase]     + bb[rowbase];
        bias.y = ba[rowbase + 1] + bb[rowbase + 1];
    }
    float creg = 0.0f;   // cell state (warp 0, lanes < 8)
    __syncthreads();

    for (int s = 0; s < STEPS; s++) {
        float2 part = make_float2(0.f, 0.f);
        if (lane < NCH)
            part = *(const float2*)&g_xgp[(long)lane * STEPS * G4 + (long)s * G4 + rowbase];
        else if (lane == 16)
            part = bias;

        float a0 = part.x, a1 = part.y;
        if (s > 0) {
            const ull* src = (const ull*)(hseq + (s - 1) * HID) + t;
            ull hv;
            uint2 u;
            do {
                hv = ld_relaxed_b64(src);
                u  = *(uint2*)&hv;
            } while (u.x == SENT || u.y == SENT);
            ((ull*)hsh)[t] = hv;
            __syncthreads();   // staging sync

            ull acc0 = 0ull, acc1 = 0ull;
#pragma unroll
            for (int p = 0; p < 16; p++) {
                ull h2 = *(const ull*)&hsh[p * 64 + lane * 2];
                acc0 = fma2(w0[p], h2, acc0);
                acc1 = fma2(w1[p], h2, acc1);
            }
            float2 f0 = unpack2(acc0), f1 = unpack2(acc1);
            a0 += f0.x + f0.y;
            a1 += f1.x + f1.y;
        }
#pragma unroll
        for (int o = 16; o > 0; o >>= 1) {
            a0 += __shfl_down_sync(0xffffffffu, a0, o);
            a1 += __shfl_down_sync(0xffffffffu, a1, o);
        }
        if (lane == 0) {
            // apply THIS gate's activation here (parallel across 16 warps)
            float act0, act1;
            if (g == 2) { act0 = tanhfast(a0); act1 = tanhfast(a1); }
            else        { act0 = sigf(a0);     act1 = sigf(a1);     }
            graw[(jh * 2 + 0) * 4 + g] = act0;
            graw[(jh * 2 + 1) * 4 + g] = act1;
        }
        __syncthreads();   // (A)

        if (w == 0 && lane < 8) {
            // graw already activated: short tail
            float4 v = *(const float4*)&graw[lane * 4];   // i,f,g,o
            creg = fmaf(v.y, creg, v.x * v.z);
            st_relaxed_f32(&hseq[s * HID + r * 8 + lane], v.w * tanhfast(creg));
        }
        // no end-of-step sync (ordering via poll-gating; proven in R8)
    }
}

// ============================================================
// FC2 fused with fc1 partial-reduce + bias + ReLU. One CTA per s.
// ============================================================
__global__ __launch_bounds__(128)
void fc2_k(const float* __restrict__ W2, const float* __restrict__ b2,
           const float* __restrict__ b1, float* __restrict__ out)
{
    __shared__ __align__(16) float zsh[512];
    const int s = blockIdx.x;
    const int t = threadIdx.x, lane = t & 31, w = t >> 5;

    {
        const long base = (long)s * 512 + t * 4;
        float4 z = *(const float4*)&b1[t * 4];
#pragma unroll
        for (int c = 0; c < NCH; c++) {
            float4 p = *(const float4*)&g_zp[base + (long)c * STEPS * 512];
            z.x += p.x; z.y += p.y; z.z += p.z; z.w += p.w;
        }
        z.x = fmaxf(z.x, 0.f); z.y = fmaxf(z.y, 0.f);
        z.z = fmaxf(z.z, 0.f); z.w = fmaxf(z.w, 0.f);
        *(float4*)&zsh[t * 4] = z;
    }
    __syncthreads();

    for (int c = w; c < CC; c += 4) {
        float acc = 0.f;
#pragma unroll
        for (int k = 0; k < 16; k++)
            acc = fmaf(zsh[k * 32 + lane], W2[c * 512 + k * 32 + lane], acc);
#pragma unroll
        for (int o = 16; o > 0; o >>= 1)
            acc += __shfl_down_sync(0xffffffffu, acc, o);
        if (lane == 0) out[s * CC + c] = acc + b2[c];
    }
}

// ============================================================
extern "C" void kernel_launch(void* const* d_in, const int* in_sizes, int n_in,
                              void* d_out, int out_size)
{
    const float* x    = (const float*)d_in[0];
    const float* Wih0 = (const float*)d_in[1];
    const float* Whh0 = (const float*)d_in[2];
    const float* bih0 = (const float*)d_in[3];
    const float* bhh0 = (const float*)d_in[4];
    const float* Wih1 = (const float*)d_in[5];
    const float* Whh1 = (const float*)d_in[6];
    const float* bih1 = (const float*)d_in[7];
    const float* bhh1 = (const float*)d_in[8];
    const float* W1   = (const float*)d_in[9];
    const float* b1   = (const float*)d_in[10];
    const float* W2   = (const float*)d_in[11];
    const float* b2   = (const float*)d_in[12];
    float* out = (float*)d_out;

    reset_kernel<<<256, 256>>>();                    // sentinel-fill h buffers
    gemmcp_k<<<128 * NCH, 128>>>(0, x, Wih0);        // xg partials, layer 1
    lstm_rec<<<NB, 512>>>(Whh0, bih0, bhh0, 0);
    gemmcp_k<<<128 * NCH, 128>>>(1, nullptr, Wih1);  // xg partials, layer 2
    lstm_rec<<<NB, 512>>>(Whh1, bih1, bhh1, 1);
    gemmcp_k<<<16 * NCH, 128>>>(2, nullptr, W1);     // fc1 partials
    fc2_k<<<64, 128>>>(W2, b2, b1, out);             // reduce+relu+fc2
}

// round 16
// speedup vs baseline: 1.2157x; 1.2157x over previous
#include <cuda_runtime.h>

// Shapes: seq=64 steps (orig B), only batch-row t=255 of T=256 matters.
#define STEPS 64
#define HID   1024
#define G4    4096
#define TT    256
#define DD    1024
#define CC    27
#define NB    128          // recurrence CTAs (1/SM, co-resident)
#define NCH   8            // GEMM K-split chunks
#define KC    128          // k per chunk
#define SENT  0xFFC0DEADu  // NaN payload: impossible LSTM output bit pattern

typedef unsigned long long ull;
typedef unsigned int uint;

// ---- scratch (device globals; no allocation) ----
__device__ __align__(16) float g_xgp[(long)NCH * STEPS * G4];  // gate-preact partials
__device__ __align__(16) float g_h1 [STEPS * HID];
__device__ __align__(16) float g_h2 [STEPS * HID];
__device__ __align__(16) float g_zp [NCH * STEPS * 512];       // fc1 partials

__global__ void reset_kernel() {
    int i = blockIdx.x * 256 + threadIdx.x;   // 256x256 = 65536 = STEPS*HID
    ((uint*)g_h1)[i] = SENT;
    ((uint*)g_h2)[i] = SENT;
}

__device__ __forceinline__ float sigf(float x)     { return 1.0f / (1.0f + __expf(-x)); }
__device__ __forceinline__ float tanhfast(float x) { return 2.0f / (1.0f + __expf(-2.0f * x)) - 1.0f; }

__device__ __forceinline__ ull fma2(ull a, ull b, ull c) {
    ull d;
    asm("fma.rn.f32x2 %0, %1, %2, %3;" : "=l"(d) : "l"(a), "l"(b), "l"(c));
    return d;
}
__device__ __forceinline__ float2 unpack2(ull v) {
    float2 f;
    asm("mov.b64 {%0, %1}, %2;" : "=f"(f.x), "=f"(f.y) : "l"(v));
    return f;
}
// morally-strong relaxed atomics (gpu scope) for the racing h exchange
__device__ __forceinline__ ull ld_relaxed_b64(const ull* p) {
    ull v;
    asm volatile("ld.relaxed.gpu.global.b64 %0, [%1];" : "=l"(v) : "l"(p) : "memory");
    return v;
}
__device__ __forceinline__ void st_relaxed_f32(float* p, float v) {
    asm volatile("st.relaxed.gpu.global.f32 [%0], %1;" :: "l"(p), "f"(v) : "memory");
}
__device__ __forceinline__ void cp_async16(void* smem_dst, const void* gptr) {
    uint a = (uint)__cvta_generic_to_shared(smem_dst);
    asm volatile("cp.async.cg.shared.global [%0], [%1], 16;" :: "r"(a), "l"(gptr) : "memory");
}

// ============================================================
// K-split (x8) tiled GEMM — W streamed via cp.async (double-buffered
// 32-k tiles), X via register prefetch + smem transpose, and
// COALESCED output (acc -> smem transpose -> STG.128 along rows).
//   mode 0: X = x[:,255,:] (stride T*D), rows=4096 -> g_xgp   grid 1024
//   mode 1: X = g_h1,                    rows=4096 -> g_xgp   grid 1024
//   mode 2: X = g_h2,                    rows=512  -> g_zp    grid 128
// 128 threads, 32-row x 64-s tile, thread tile 4x4.
// ============================================================
__global__ __launch_bounds__(128)
void gemmcp_k(int mode, const float* __restrict__ xin, const float* __restrict__ W)
{
    __shared__ __align__(16) float WsR[2][32 * 36];   // [buf][row*36 + k]  9.2KB
    __shared__ __align__(16) float Xs [2][32][68];    // [buf][k][s]       17.4KB

    const float* X;
    long xbase, xstride;
    float* pout;
    int nrows, ntiles;
    if (mode == 0)      { X = xin;  xbase = 255L * DD; xstride = (long)TT * DD; pout = g_xgp; nrows = G4;  ntiles = 128; }
    else if (mode == 1) { X = g_h1; xbase = 0;         xstride = HID;           pout = g_xgp; nrows = G4;  ntiles = 128; }
    else                { X = g_h2; xbase = 0;         xstride = HID;           pout = g_zp;  nrows = 512; ntiles = 16;  }

    const int chunk = blockIdx.x / ntiles;
    const int rb    = (blockIdx.x % ntiles) * 32;
    pout += (long)chunk * STEPS * nrows;

    const int t  = threadIdx.x;
    const int tr = t >> 4;
    const int tc = t & 15;
    const int k0 = chunk * KC;

    // W cp.async coords: 256 16B-chunks per tile, 2 per thread
    const int wr0 = t >> 3,          wk0 = (t & 7) * 4;
    const int wr1 = (t + 128) >> 3,  wk1 = ((t + 128) & 7) * 4;
    // X reg-prefetch coords: 4 float4 per thread
    int xs_s[4], xs_kq[4];
#pragma unroll
    for (int i = 0; i < 4; i++) { int e = t + i * 128; xs_s[i] = e >> 3; xs_kq[i] = (e & 7) * 4; }

    // prologue: cp.async W tile0 + reg-load X tile0
    cp_async16(&WsR[0][wr0 * 36 + wk0], &W[(long)(rb + wr0) * 1024 + k0 + wk0]);
    cp_async16(&WsR[0][wr1 * 36 + wk1], &W[(long)(rb + wr1) * 1024 + k0 + wk1]);
    asm volatile("cp.async.commit_group;" ::: "memory");
    float4 xA[4];
#pragma unroll
    for (int i = 0; i < 4; i++)
        xA[i] = *(const float4*)&X[xbase + (long)xs_s[i] * xstride + k0 + xs_kq[i]];

    float acc[4][4];
#pragma unroll
    for (int i = 0; i < 4; i++)
#pragma unroll
        for (int j = 0; j < 4; j++) acc[i][j] = 0.0f;

#pragma unroll
    for (int tile = 0; tile < 4; tile++) {
        const int buf = tile & 1;
        // commit X tile (transpose scatter into Xs[buf])
#pragma unroll
        for (int i = 0; i < 4; i++) {
            Xs[buf][xs_kq[i] + 0][xs_s[i]] = xA[i].x;
            Xs[buf][xs_kq[i] + 1][xs_s[i]] = xA[i].y;
            Xs[buf][xs_kq[i] + 2][xs_s[i]] = xA[i].z;
            Xs[buf][xs_kq[i] + 3][xs_s[i]] = xA[i].w;
        }
        // issue W tile+1 into other buffer, then retire W tile
        if (tile < 3) {
            const int kt = k0 + (tile + 1) * 32;
            cp_async16(&WsR[buf ^ 1][wr0 * 36 + wk0], &W[(long)(rb + wr0) * 1024 + kt + wk0]);
            cp_async16(&WsR[buf ^ 1][wr1 * 36 + wk1], &W[(long)(rb + wr1) * 1024 + kt + wk1]);
            asm volatile("cp.async.commit_group;" ::: "memory");
            asm volatile("cp.async.wait_group 1;" ::: "memory");
        } else {
            asm volatile("cp.async.wait_group 0;" ::: "memory");
        }
        __syncthreads();   // W tile + X tile visible to all

        // reg-load X tile+1 (overlaps FMA below)
        if (tile < 3) {
            const int kt = k0 + (tile + 1) * 32;
#pragma unroll
            for (int i = 0; i < 4; i++)
                xA[i] = *(const float4*)&X[xbase + (long)xs_s[i] * xstride + kt + xs_kq[i]];
        }

        // FMA: k-quads; W row-major reads (2 rows/warp -> conflict-free)
#pragma unroll
        for (int kq = 0; kq < 8; kq++) {
            float xf[4][4];   // [q][j]
#pragma unroll
            for (int q = 0; q < 4; q++) {
                float4 v = *(const float4*)&Xs[buf][kq * 4 + q][tc * 4];
                xf[q][0] = v.x; xf[q][1] = v.y; xf[q][2] = v.z; xf[q][3] = v.w;
            }
            float wf[4][4];   // [i][q]
#pragma unroll
            for (int i = 0; i < 4; i++) {
                float4 v = *(const float4*)&WsR[buf][(tr * 4 + i) * 36 + kq * 4];
                wf[i][0] = v.x; wf[i][1] = v.y; wf[i][2] = v.z; wf[i][3] = v.w;
            }
#pragma unroll
            for (int i = 0; i < 4; i++)
#pragma unroll
                for (int j = 0; j < 4; j++) {
                    acc[i][j] = fmaf(wf[i][0], xf[0][j], acc[i][j]);
                    acc[i][j] = fmaf(wf[i][1], xf[1][j], acc[i][j]);
                    acc[i][j] = fmaf(wf[i][2], xf[2][j], acc[i][j]);
                    acc[i][j] = fmaf(wf[i][3], xf[3][j], acc[i][j]);
                }
        }
        __syncthreads();   // buffer reuse guard
    }

    // ---- coalesced output: acc -> smem[row][s] -> STG.128 along rows ----
    {
        float (*ob)[68] = Xs[0];   // 32 rows x 68 (reuse; all FMA reads done)
#pragma unroll
        for (int i = 0; i < 4; i++)
            *(float4*)&ob[tr * 4 + i][tc * 4] =
                make_float4(acc[i][0], acc[i][1], acc[i][2], acc[i][3]);
        __syncthreads();

        const int s_i  = t >> 1;        // 0..63
        const int half = t & 1;         // 0..1 -> rows half*16 .. half*16+15
#pragma unroll
        for (int q = 0; q < 4; q++) {
            const int row = half * 16 + q * 4;
            float4 o = make_float4(ob[row + 0][s_i], ob[row + 1][s_i],
                                   ob[row + 2][s_i], ob[row + 3][s_i]);
            *(float4*)&pout[(long)s_i * nrows + rb + row] = o;
        }
    }
}

// ============================================================
// Persistent LSTM recurrence (VERBATIM R11/R14 — proven at 227.8us).
// 128 CTAs x 512 threads (16 warps), Whh in packed-f32x2 registers,
// h exchange via sentinel-polled relaxed b64 atomics, 2 syncs/step.
// ============================================================
__global__ __launch_bounds__(512, 1)
void lstm_rec(const float* __restrict__ Whh,
              const float* __restrict__ ba, const float* __restrict__ bb,
              int layer)
{
    __shared__ __align__(16) float hsh[HID];
    __shared__ float graw[32];   // [unit*4 + gate]
    __shared__ float gact[32];

    float* hseq = layer ? g_h2 : g_h1;
    const int r    = blockIdx.x;
    const int t    = threadIdx.x;
    const int lane = t & 31;
    const int w    = t >> 5;       // 0..15
    const int g    = w & 3;
    const int jh   = w >> 2;       // 0..3
    const int rowbase = (g << 10) + (r << 3) + (jh << 1);   // 2 rows

    ull w0[16], w1[16];
#pragma unroll
    for (int p = 0; p < 16; p++) {
        long o = (long)rowbase * 1024 + p * 64 + lane * 2;
        w0[p] = *(const ull*)(Whh + o);
        w1[p] = *(const ull*)(Whh + o + 1024);
    }
    float2 bias = make_float2(0.f, 0.f);
    if (lane == 16) {
        bias.x = ba[rowbase]     + bb[rowbase];
        bias.y = ba[rowbase + 1] + bb[rowbase + 1];
    }
    float creg = 0.0f;   // cell state (warp 0, lanes < 8)
    __syncthreads();

    for (int s = 0; s < STEPS; s++) {
        float2 part = make_float2(0.f, 0.f);
        if (lane < NCH)
            part = *(const float2*)&g_xgp[(long)lane * STEPS * G4 + (long)s * G4 + rowbase];
        else if (lane == 16)
            part = bias;

        float a0 = part.x, a1 = part.y;
        if (s > 0) {
            const ull* src = (const ull*)(hseq + (s - 1) * HID) + t;
            ull hv;
            uint2 u;
            do {
                hv = ld_relaxed_b64(src);
                u  = *(uint2*)&hv;
            } while (u.x == SENT || u.y == SENT);
            ((ull*)hsh)[t] = hv;
            __syncthreads();   // staging sync

            ull acc0 = 0ull, acc1 = 0ull;
#pragma unroll
            for (int p = 0; p < 16; p++) {
                ull h2 = *(const ull*)&hsh[p * 64 + lane * 2];
                acc0 = fma2(w0[p], h2, acc0);
                acc1 = fma2(w1[p], h2, acc1);
            }
            float2 f0 = unpack2(acc0), f1 = unpack2(acc1);
            a0 += f0.x + f0.y;
            a1 += f1.x + f1.y;
        }
#pragma unroll
        for (int o = 16; o > 0; o >>= 1) {
            a0 += __shfl_down_sync(0xffffffffu, a0, o);
            a1 += __shfl_down_sync(0xffffffffu, a1, o);
        }
        if (lane == 0) {
            graw[(jh * 2 + 0) * 4 + g] = a0;
            graw[(jh * 2 + 1) * 4 + g] = a1;
        }
        __syncthreads();   // (A)

        if (w == 0) {
            float v = graw[lane];                       // lane = unit*4 + gate
            gact[lane] = ((lane & 3) == 2) ? tanhfast(v) : sigf(v);
            __syncwarp();
            if (lane < 8) {
                float iv = gact[lane * 4 + 0];
                float fv = gact[lane * 4 + 1];
                float gv = gact[lane * 4 + 2];
                float ov = gact[lane * 4 + 3];
                creg = fmaf(fv, creg, iv * gv);
                st_relaxed_f32(&hseq[s * HID + r * 8 + lane], ov * tanhfast(creg));
            }
        }
        // no end-of-step sync (ordering via poll-gating; proven in R8)
    }
}

// ============================================================
// FC2 fused with fc1 partial-reduce + bias + ReLU. One CTA per s.
// ============================================================
__global__ __launch_bounds__(128)
void fc2_k(const float* __restrict__ W2, const float* __restrict__ b2,
           const float* __restrict__ b1, float* __restrict__ out)
{
    __shared__ __align__(16) float zsh[512];
    const int s = blockIdx.x;
    const int t = threadIdx.x, lane = t & 31, w = t >> 5;

    {
        const long base = (long)s * 512 + t * 4;
        float4 z = *(const float4*)&b1[t * 4];
#pragma unroll
        for (int c = 0; c < NCH; c++) {
            float4 p = *(const float4*)&g_zp[base + (long)c * STEPS * 512];
            z.x += p.x; z.y += p.y; z.z += p.z; z.w += p.w;
        }
        z.x = fmaxf(z.x, 0.f); z.y = fmaxf(z.y, 0.f);
        z.z = fmaxf(z.z, 0.f); z.w = fmaxf(z.w, 0.f);
        *(float4*)&zsh[t * 4] = z;
    }
    __syncthreads();

    for (int c = w; c < CC; c += 4) {
        float acc = 0.f;
#pragma unroll
        for (int k = 0; k < 16; k++)
            acc = fmaf(zsh[k * 32 + lane], W2[c * 512 + k * 32 + lane], acc);
#pragma unroll
        for (int o = 16; o > 0; o >>= 1)
            acc += __shfl_down_sync(0xffffffffu, acc, o);
        if (lane == 0) out[s * CC + c] = acc + b2[c];
    }
}

// ============================================================
extern "C" void kernel_launch(void* const* d_in, const int* in_sizes, int n_in,
                              void* d_out, int out_size)
{
    const float* x    = (const float*)d_in[0];
    const float* Wih0 = (const float*)d_in[1];
    const float* Whh0 = (const float*)d_in[2];
    const float* bih0 = (const float*)d_in[3];
    const float* bhh0 = (const float*)d_in[4];
    const float* Wih1 = (const float*)d_in[5];
    const float* Whh1 = (const float*)d_in[6];
    const float* bih1 = (const float*)d_in[7];
    const float* bhh1 = (const float*)d_in[8];
    const float* W1   = (const float*)d_in[9];
    const float* b1   = (const float*)d_in[10];
    const float* W2   = (const float*)d_in[11];
    const float* b2   = (const float*)d_in[12];
    float* out = (float*)d_out;

    reset_kernel<<<256, 256>>>();                    // sentinel-fill h buffers
    gemmcp_k<<<128 * NCH, 128>>>(0, x, Wih0);        // xg partials, layer 1
    lstm_rec<<<NB, 512>>>(Whh0, bih0, bhh0, 0);
    gemmcp_k<<<128 * NCH, 128>>>(1, nullptr, Wih1);  // xg partials, layer 2
    lstm_rec<<<NB, 512>>>(Whh1, bih1, bhh1, 1);
    gemmcp_k<<<16 * NCH, 128>>>(2, nullptr, W1);     // fc1 partials
    fc2_k<<<64, 128>>>(W2, b2, b1, out);             // reduce+relu+fc2
}